// round 2
// baseline (speedup 1.0000x reference)
#include <cuda_runtime.h>
#include <cuda_bf16.h>

// Problem constants (match reference)
#define BB   64
#define CC   2
#define LL   64
#define NBIN 16
#define NVOX (LL*LL*LL)        // 262144
#define NB2  (NBIN*NBIN)       // 256 bins
#define EPSV 1e-5f

// Scratch (no allocations allowed): bin table + per-(b,c) bin sums
__device__ unsigned char g_bins[NVOX];
__device__ float g_scratch[BB*CC*NB2];   // 32768 floats

// ---------------------------------------------------------------------------
// Kernel A: build the (voxel -> bin) table exactly as the reference does,
// and zero the scatter scratch. Runs every launch (graph-captured), ~2us.
// ---------------------------------------------------------------------------
__global__ __launch_bounds__(256) void build_tables_kernel() {
    int v = blockIdx.x * blockDim.x + threadIdx.x;
    if (v < NVOX) {
        float fi = (float)(v >> 12);
        float fj = (float)((v >> 6) & 63);
        float fk = (float)(v & 63);
        // exact integer squares -> exact f32 sums; __fsqrt_rn = correctly rounded
        float xc = __fsqrt_rn(fj*fj + fk*fk);
        float zc = __fsqrt_rn(fj*fj + fi*fi);
        const float deg = 57.29577951308232f;   // 180/pi, f32
        // mirror reference: floor(atan2(.,.) * deg / 22)
        float ra = __fdiv_rn(__fmul_rn(atan2f(xc, fi), deg), 22.0f);
        float rz = __fdiv_rn(__fmul_rn(atan2f(fk, zc), deg), 22.0f);
        int ax = (int)floorf(ra);
        int az = (int)floorf(rz);
        g_bins[v] = (unsigned char)(ax * NBIN + az);
    }
    if (v < BB*CC*NB2) g_scratch[v] = 0.0f;
}

// ---------------------------------------------------------------------------
// Kernel B: streaming weighted histogram.
//   For each (b,c) pair, sum x[v]*mag[v] into 256 bins.
//   - float4 coalesced loads of x, uchar4 loads of the bin table (L2 hits)
//   - mag recomputed inline (bit-exact with reference sqrt)
//   - per-lane run combining + warp segmented aggregation so shared atomics
//     are ~1-6 per 128 elements instead of 128 (avoids 32-way ATOMS conflicts)
// ---------------------------------------------------------------------------
#define SPLIT 16                      // blocks per (b,c) pair
#define BTHREADS 256

__global__ __launch_bounds__(BTHREADS) void accumulate_kernel(const float* __restrict__ x) {
    __shared__ float hist[NB2];
    const int t = threadIdx.x;
    const int lane = t & 31;
    for (int p = t; p < NB2; p += BTHREADS) hist[p] = 0.0f;
    __syncthreads();

    const int pair = blockIdx.x / SPLIT;     // b*C + c  (x layout is pair-major)
    const int part = blockIdx.x % SPLIT;
    const int chunk = NVOX / SPLIT;          // 16384 elements
    const int base_v = part * chunk;
    const float* xp = x + (size_t)pair * NVOX;
    const unsigned full = 0xffffffffu;

    for (int off = t * 4; off < chunk; off += BTHREADS * 4) {
        int v = base_v + off;
        float4 xv = *reinterpret_cast<const float4*>(xp + v);
        uchar4 bq = *reinterpret_cast<const uchar4*>(g_bins + v);

        float fi = (float)(v >> 12);
        float fj = (float)((v >> 6) & 63);
        float fk = (float)(v & 63);          // v%4==0 so k..k+3 stay in-row
        float s2 = fi*fi + fj*fj;
        float m0 = __fsqrt_rn(s2 + fk*fk);
        float m1 = __fsqrt_rn(s2 + (fk+1.0f)*(fk+1.0f));
        float m2 = __fsqrt_rn(s2 + (fk+2.0f)*(fk+2.0f));
        float m3 = __fsqrt_rn(s2 + (fk+3.0f)*(fk+3.0f));

        float v0 = xv.x * m0, v1 = xv.y * m1, v2 = xv.z * m2, v3 = xv.w * m3;
        int b0 = bq.x, b1 = bq.y, b2 = bq.z, b3 = bq.w;

        // per-lane run combine (bins are piecewise constant along k)
        float acc = v0; int cur = b0;
        if (b1 == cur) acc += v1; else { atomicAdd(&hist[cur], acc); cur = b1; acc = v1; }
        if (b2 == cur) acc += v2; else { atomicAdd(&hist[cur], acc); cur = b2; acc = v2; }
        if (b3 == cur) acc += v3; else { atomicAdd(&hist[cur], acc); cur = b3; acc = v3; }

        // warp segmented aggregation: group adjacent lanes with equal bin
        int prev = __shfl_up_sync(full, cur, 1);
        bool head = (lane == 0) || (prev != cur);
        unsigned hm = __ballot_sync(full, head);

        // plain inclusive scan of acc
        float sc = acc;
        #pragma unroll
        for (int d = 1; d < 32; d <<= 1) {
            float y = __shfl_up_sync(full, sc, d);
            if (lane >= d) sc += y;
        }
        // segment start = highest head bit <= lane (bit 0 always set)
        unsigned below = hm & (0xffffffffu >> (31 - lane));
        int st = 31 - __clz(below);
        bool endl = (lane == 31) || ((hm >> (lane + 1)) & 1u);
        float before = __shfl_sync(full, sc, (st > 0) ? (st - 1) : 0);
        float total = sc - ((st > 0) ? before : 0.0f);
        if (endl) atomicAdd(&hist[cur], total);
    }

    __syncthreads();
    for (int p = t; p < NB2; p += BTHREADS) {
        float val = hist[p];
        if (val != 0.0f) atomicAdd(&g_scratch[pair * NB2 + p], val);
    }
}

// ---------------------------------------------------------------------------
// Kernel C: per-channel group norm over (B, N, N) = 16384 values per channel.
// Two-pass (mean, then var) to match reference numerics. One block per channel.
// ---------------------------------------------------------------------------
__global__ __launch_bounds__(512) void gn_kernel(const float* __restrict__ gamma,
                                                 const float* __restrict__ beta,
                                                 float* __restrict__ out) {
    const int c = blockIdx.x;
    const int t = threadIdx.x;          // 512 threads
    const int lane = t & 31, warp = t >> 5;
    const unsigned full = 0xffffffffu;

    __shared__ float red[16];
    __shared__ float s_mean, s_rs;

    float vals[32];
    float sum = 0.0f;
    #pragma unroll
    for (int i = 0; i < 32; i++) {
        int idx = i * 512 + t;                       // coalesced
        int b = idx >> 8, p = idx & 255;
        float g = g_scratch[(b * CC + c) * NB2 + p];
        vals[i] = g;
        sum += g;
    }
    #pragma unroll
    for (int d = 16; d; d >>= 1) sum += __shfl_down_sync(full, sum, d);
    if (lane == 0) red[warp] = sum;
    __syncthreads();
    if (t == 0) {
        float tot = 0.0f;
        #pragma unroll
        for (int w = 0; w < 16; w++) tot += red[w];
        s_mean = tot * (1.0f / 16384.0f);
    }
    __syncthreads();
    float mean = s_mean;

    float vs = 0.0f;
    #pragma unroll
    for (int i = 0; i < 32; i++) {
        float d = vals[i] - mean;
        vs = fmaf(d, d, vs);
    }
    #pragma unroll
    for (int d = 16; d; d >>= 1) vs += __shfl_down_sync(full, vs, d);
    __syncthreads();                     // red[] reuse
    if (lane == 0) red[warp] = vs;
    __syncthreads();
    if (t == 0) {
        float tot = 0.0f;
        #pragma unroll
        for (int w = 0; w < 16; w++) tot += red[w];
        float var = tot * (1.0f / 16384.0f);
        s_rs = rsqrtf(var + EPSV);
    }
    __syncthreads();
    float rs = s_rs;
    float ga = gamma[c], be = beta[c];

    #pragma unroll
    for (int i = 0; i < 32; i++) {
        int idx = i * 512 + t;
        int b = idx >> 8, p = idx & 255;
        out[(b * CC + c) * NB2 + p] = (vals[i] - mean) * rs * ga + be;
    }
}

// ---------------------------------------------------------------------------
extern "C" void kernel_launch(void* const* d_in, const int* in_sizes, int n_in,
                              void* d_out, int out_size) {
    const float* x     = (const float*)d_in[0];   // [64, 2*64^3]
    const float* gamma = (const float*)d_in[1];   // [2]
    const float* beta  = (const float*)d_in[2];   // [2]
    float* out = (float*)d_out;                   // [64,2,16,16] f32

    build_tables_kernel<<<(NVOX + 255) / 256, 256>>>();
    accumulate_kernel<<<BB * CC * SPLIT, BTHREADS>>>(x);
    gn_kernel<<<CC, 512>>>(gamma, beta, out);
}

// round 3
// speedup vs baseline: 1.7184x; 1.7184x over previous
#include <cuda_runtime.h>
#include <cuda_bf16.h>

// Problem constants (match reference)
#define BB   64
#define CC   2
#define LL   64
#define NBIN 16
#define NVOX (LL*LL*LL)        // 262144
#define NPAIR (BB*CC)          // 128
#define NDENSE 25              // only ax,az in 0..4 ever occur
#define DSTRIDE 32             // padded scratch stride per pair
#define EPSV 1e-5f

// Scratch (no allocations allowed)
__device__ unsigned char g_bins[NVOX];            // DENSE bin id: ax*5+az in 0..24
__device__ float g_scratch[NPAIR*DSTRIDE];        // per-(b,c) dense bin sums

// ---------------------------------------------------------------------------
// Kernel A: voxel -> dense bin table (exactly mirroring reference atan2 math),
// and zero the scatter scratch. 2 voxels/thread for ILP.
// ---------------------------------------------------------------------------
__global__ __launch_bounds__(256) void build_tables_kernel() {
    int base = (blockIdx.x * blockDim.x + threadIdx.x) * 2;
    #pragma unroll
    for (int u = 0; u < 2; u++) {
        int v = base + u;
        if (v < NVOX) {
            float fi = (float)(v >> 12);
            float fj = (float)((v >> 6) & 63);
            float fk = (float)(v & 63);
            float xc = __fsqrt_rn(fj*fj + fk*fk);
            float zc = __fsqrt_rn(fj*fj + fi*fi);
            const float deg = 57.29577951308232f;   // 180/pi
            float ra = __fdiv_rn(__fmul_rn(atan2f(xc, fi), deg), 22.0f);
            float rz = __fdiv_rn(__fmul_rn(atan2f(fk, zc), deg), 22.0f);
            int ax = (int)floorf(ra);   // 0..4
            int az = (int)floorf(rz);   // 0..4
            g_bins[v] = (unsigned char)(ax * 5 + az);
        }
    }
    int t = blockIdx.x * blockDim.x + threadIdx.x;
    if (t < NPAIR*DSTRIDE) g_scratch[t] = 0.0f;
}

// ---------------------------------------------------------------------------
// Kernel B: streaming weighted histogram with per-thread PRIVATE dense
// histograms in SMEM (no atomics, no shuffles in the hot loop).
//   - float4 coalesced x loads, uchar4 dense-bin loads (L2-resident table)
//   - mag recomputed inline with __fsqrt_rn (bit-exact vs reference)
//   - run-combine along k (bins are non-decreasing along k), each closed run
//     goes to hist[t*25+bin]: stride 25 is coprime with 32 banks, so even
//     all-lanes-same-bin updates are conflict-free.
//   - block flush: tree-reduce 256 private hists, 25 global atomics/block
// ---------------------------------------------------------------------------
#define SPLIT 16                       // blocks per (b,c) pair
#define CHUNK (NVOX / SPLIT)           // 16384 elements
#define BTHREADS 256

__global__ __launch_bounds__(BTHREADS) void accumulate_kernel(const float* __restrict__ x) {
    __shared__ float hist[BTHREADS * NDENSE];     // 25.6 KB
    const int t = threadIdx.x;
    float* h = &hist[t * NDENSE];
    #pragma unroll
    for (int i = 0; i < NDENSE; i++) h[i] = 0.0f;
    // private region per thread -> no sync needed before the loop

    const int pair = blockIdx.x >> 4;             // b*C + c
    const int part = blockIdx.x & (SPLIT - 1);
    const int vbase = part * CHUNK;
    const float* xp = x + (size_t)pair * NVOX + vbase;
    const unsigned char* bp = g_bins + vbase;

    #pragma unroll 4
    for (int off = t * 4; off < CHUNK; off += BTHREADS * 4) {
        float4 xv = *reinterpret_cast<const float4*>(xp + off);
        uchar4 bq = *reinterpret_cast<const uchar4*>(bp + off);

        int v = vbase + off;
        float fi = (float)(v >> 12);
        float fj = (float)((v >> 6) & 63);
        float fk = (float)(v & 63);               // off%4==0 -> k..k+3 in-row
        float s2 = fi*fi + fj*fj;
        float m0 = __fsqrt_rn(s2 + fk*fk);
        float m1 = __fsqrt_rn(s2 + (fk+1.0f)*(fk+1.0f));
        float m2 = __fsqrt_rn(s2 + (fk+2.0f)*(fk+2.0f));
        float m3 = __fsqrt_rn(s2 + (fk+3.0f)*(fk+3.0f));

        float v0 = xv.x * m0, v1 = xv.y * m1, v2 = xv.z * m2, v3 = xv.w * m3;
        int b0 = bq.x, b1 = bq.y, b2 = bq.z, b3 = bq.w;

        // per-lane run combine; closed runs go to the private histogram
        float acc = v0; int cur = b0;
        if (b1 == cur) acc += v1; else { h[cur] += acc; cur = b1; acc = v1; }
        if (b2 == cur) acc += v2; else { h[cur] += acc; cur = b2; acc = v2; }
        if (b3 == cur) acc += v3; else { h[cur] += acc; cur = b3; acc = v3; }
        h[cur] += acc;
    }

    __syncthreads();

    // Flush: 8 warps; warp w reduces bins {w, w+8, w+16, w+24} over 256 threads
    const int warp = t >> 5, lane = t & 31;
    const unsigned full = 0xffffffffu;
    for (int bin = warp; bin < NDENSE; bin += 8) {
        float s = 0.0f;
        #pragma unroll
        for (int j = 0; j < 8; j++)
            s += hist[(lane + 32*j) * NDENSE + bin];
        #pragma unroll
        for (int d = 16; d; d >>= 1) s += __shfl_down_sync(full, s, d);
        if (lane == 0) atomicAdd(&g_scratch[pair * DSTRIDE + bin], s);
    }
}

// ---------------------------------------------------------------------------
// Kernel C: per-channel group norm over (B, 16, 16) = 16384 values, of which
// only 64*25 are (possibly) nonzero. Two-pass mean/var; zero bins contribute
// analytically: var += (16384 - 64*25) * mean^2.
// One block per channel.
// ---------------------------------------------------------------------------
__global__ __launch_bounds__(256) void gn_kernel(const float* __restrict__ gamma,
                                                 const float* __restrict__ beta,
                                                 float* __restrict__ out) {
    const int c = blockIdx.x;
    const int t = threadIdx.x;
    const int lane = t & 31, warp = t >> 5;
    const unsigned full = 0xffffffffu;

    __shared__ float red[8];
    __shared__ float s_mean, s_rs;

    // dense values for this channel: 64 batches x 25 bins = 1600
    float vals[7];                      // ceil(1600/256) = 7 slots
    float sum = 0.0f;
    #pragma unroll
    for (int i = 0; i < 7; i++) {
        int idx = i * 256 + t;
        float g = 0.0f;
        if (idx < BB * NDENSE) {
            int b = idx / NDENSE, d = idx % NDENSE;
            g = g_scratch[(b * CC + c) * DSTRIDE + d];
        }
        vals[i] = g;
        sum += g;
    }
    #pragma unroll
    for (int d = 16; d; d >>= 1) sum += __shfl_down_sync(full, sum, d);
    if (lane == 0) red[warp] = sum;
    __syncthreads();
    if (t == 0) {
        float tot = 0.0f;
        #pragma unroll
        for (int w = 0; w < 8; w++) tot += red[w];
        s_mean = tot * (1.0f / (BB * NBIN * NBIN));
    }
    __syncthreads();
    float mean = s_mean;

    float vs = 0.0f;
    #pragma unroll
    for (int i = 0; i < 7; i++) {
        int idx = i * 256 + t;
        if (idx < BB * NDENSE) {
            float d = vals[i] - mean;
            vs = fmaf(d, d, vs);
        }
    }
    #pragma unroll
    for (int d = 16; d; d >>= 1) vs += __shfl_down_sync(full, vs, d);
    __syncthreads();
    if (lane == 0) red[warp] = vs;
    __syncthreads();
    if (t == 0) {
        float tot = 0.0f;
        #pragma unroll
        for (int w = 0; w < 8; w++) tot += red[w];
        // zero bins: (16384 - 64*25) entries each contribute mean^2
        tot += (float)(BB * NBIN * NBIN - BB * NDENSE) * s_mean * s_mean;
        float var = tot * (1.0f / (BB * NBIN * NBIN));
        s_rs = rsqrtf(var + EPSV);
    }
    __syncthreads();
    float rs = s_rs;
    float ga = gamma[c], be = beta[c];

    // write all 16384 outputs for this channel
    for (int idx = t; idx < BB * NBIN * NBIN; idx += 256) {
        int b = idx >> 8, s = idx & 255;
        int ax = s >> 4, az = s & 15;
        float g = 0.0f;
        if (ax < 5 && az < 5)
            g = g_scratch[(b * CC + c) * DSTRIDE + ax * 5 + az];
        out[(b * CC + c) * 256 + s] = (g - mean) * rs * ga + be;
    }
}

// ---------------------------------------------------------------------------
extern "C" void kernel_launch(void* const* d_in, const int* in_sizes, int n_in,
                              void* d_out, int out_size) {
    const float* x     = (const float*)d_in[0];   // [64, 2*64^3]
    const float* gamma = (const float*)d_in[1];   // [2]
    const float* beta  = (const float*)d_in[2];   // [2]
    float* out = (float*)d_out;                   // [64,2,16,16] f32

    build_tables_kernel<<<(NVOX/2 + 255) / 256, 256>>>();
    accumulate_kernel<<<NPAIR * SPLIT, BTHREADS>>>(x);
    gn_kernel<<<CC, 256>>>(gamma, beta, out);
}

// round 4
// speedup vs baseline: 1.8517x; 1.0776x over previous
#include <cuda_runtime.h>
#include <cuda_bf16.h>

// Problem constants (match reference)
#define BB   64
#define CC   2
#define LL   64
#define NBIN 16
#define NVOX (LL*LL*LL)        // 262144
#define NPAIR (BB*CC)          // 128
#define NDENSE 25              // only ax,az in 0..4 ever occur
#define DSTRIDE 32             // padded scratch stride per pair
#define EPSV 1e-5f

// Scratch (no allocations allowed)
__device__ unsigned char g_bins[NVOX];            // DENSE bin id: ax*5+az in 0..24
__device__ float g_scratch[NPAIR*DSTRIDE];        // per-(b,c) dense bin sums

// ---------------------------------------------------------------------------
// Kernel A: voxel -> dense bin table (exactly mirroring reference atan2 math),
// and zero the scatter scratch. 1 voxel/thread for max parallelism.
// ---------------------------------------------------------------------------
__global__ __launch_bounds__(256) void build_tables_kernel() {
    int v = blockIdx.x * blockDim.x + threadIdx.x;
    if (v < NVOX) {
        float fi = (float)(v >> 12);
        float fj = (float)((v >> 6) & 63);
        float fk = (float)(v & 63);
        float xc = __fsqrt_rn(fj*fj + fk*fk);
        float zc = __fsqrt_rn(fj*fj + fi*fi);
        const float deg = 57.29577951308232f;   // 180/pi
        float ra = __fdiv_rn(__fmul_rn(atan2f(xc, fi), deg), 22.0f);
        float rz = __fdiv_rn(__fmul_rn(atan2f(fk, zc), deg), 22.0f);
        int ax = (int)floorf(ra);   // 0..4
        int az = (int)floorf(rz);   // 0..4
        g_bins[v] = (unsigned char)(ax * 5 + az);
    }
    if (v < NPAIR*DSTRIDE) g_scratch[v] = 0.0f;
}

// ---------------------------------------------------------------------------
// Kernel B: streaming weighted histogram, fully BRANCHLESS hot loop.
//   - per-thread private histogram column: hist[bin*256 + t]
//     bank = t mod 32  ->  conflict-free for ANY bin pattern across lanes
//   - 8 elements per thread-iteration: 2x LDG.128 (x), 1x LDG.64 (8 bins)
//   - mag recomputed inline with __fsqrt_rn (bit-exact vs reference)
//   - unconditional hist update per element: LDS+FFMA+STS, no branches,
//     no BSSY/BSYNC, no shuffles
//   - block flush: tree-reduce + 25 global atomics per block
// ---------------------------------------------------------------------------
#define SPLIT 16                       // blocks per (b,c) pair
#define CHUNK (NVOX / SPLIT)           // 16384 elements
#define BTHREADS 256

__global__ __launch_bounds__(BTHREADS) void accumulate_kernel(const float* __restrict__ x) {
    __shared__ float hist[NDENSE * BTHREADS];     // 25.6 KB
    const int t = threadIdx.x;
    #pragma unroll
    for (int i = 0; i < NDENSE; i++) hist[i * BTHREADS + t] = 0.0f;
    // each thread touches only column t -> no sync needed before the loop

    const int pair  = blockIdx.x >> 4;            // b*C + c
    const int part  = blockIdx.x & (SPLIT - 1);
    const int vbase = part * CHUNK;
    const float* __restrict__ xp = x + (size_t)pair * NVOX + vbase;
    const unsigned char* __restrict__ bp = g_bins + vbase;

    #pragma unroll 2
    for (int off = t * 8; off < CHUNK; off += BTHREADS * 8) {
        float4 xa = *reinterpret_cast<const float4*>(xp + off);
        float4 xb = *reinterpret_cast<const float4*>(xp + off + 4);
        uint2  bq = *reinterpret_cast<const uint2*>(bp + off);

        int v = vbase + off;                      // off%8==0 -> k..k+7 in-row
        float fi = (float)(v >> 12);
        float fj = (float)((v >> 6) & 63);
        float fk = (float)(v & 63);
        float s2 = fi*fi + fj*fj;
        float m0 = __fsqrt_rn(s2 + fk*fk);
        float m1 = __fsqrt_rn(s2 + (fk+1.0f)*(fk+1.0f));
        float m2 = __fsqrt_rn(s2 + (fk+2.0f)*(fk+2.0f));
        float m3 = __fsqrt_rn(s2 + (fk+3.0f)*(fk+3.0f));
        float m4 = __fsqrt_rn(s2 + (fk+4.0f)*(fk+4.0f));
        float m5 = __fsqrt_rn(s2 + (fk+5.0f)*(fk+5.0f));
        float m6 = __fsqrt_rn(s2 + (fk+6.0f)*(fk+6.0f));
        float m7 = __fsqrt_rn(s2 + (fk+7.0f)*(fk+7.0f));

        // row offset = bin*256 = byte<<8; +t gives this thread's private cell
        hist[(( bq.x        & 0xffu) << 8) + t] += xa.x * m0;
        hist[(((bq.x >>  8) & 0xffu) << 8) + t] += xa.y * m1;
        hist[(((bq.x >> 16) & 0xffu) << 8) + t] += xa.z * m2;
        hist[(( bq.x >> 24        ) << 8) + t] += xa.w * m3;
        hist[(( bq.y        & 0xffu) << 8) + t] += xb.x * m4;
        hist[(((bq.y >>  8) & 0xffu) << 8) + t] += xb.y * m5;
        hist[(((bq.y >> 16) & 0xffu) << 8) + t] += xb.z * m6;
        hist[(( bq.y >> 24        ) << 8) + t] += xb.w * m7;
    }

    __syncthreads();

    // Flush: 8 warps; warp w handles bins {w, w+8, w+16, w+24}
    const int warp = t >> 5, lane = t & 31;
    const unsigned full = 0xffffffffu;
    for (int bin = warp; bin < NDENSE; bin += 8) {
        const float* row = &hist[bin * BTHREADS];
        float s = 0.0f;
        #pragma unroll
        for (int j = 0; j < 8; j++) s += row[lane + 32*j];
        #pragma unroll
        for (int d = 16; d; d >>= 1) s += __shfl_down_sync(full, s, d);
        if (lane == 0) atomicAdd(&g_scratch[pair * DSTRIDE + bin], s);
    }
}

// ---------------------------------------------------------------------------
// Kernel C: per-channel group norm over (B, 16, 16) = 16384 values; only
// 64*25 dense entries can be nonzero. Two-pass mean/var; zero bins enter the
// variance analytically as (16384 - 64*25) * mean^2. One block per channel.
// ---------------------------------------------------------------------------
__global__ __launch_bounds__(256) void gn_kernel(const float* __restrict__ gamma,
                                                 const float* __restrict__ beta,
                                                 float* __restrict__ out) {
    const int c = blockIdx.x;
    const int t = threadIdx.x;
    const int lane = t & 31, warp = t >> 5;
    const unsigned full = 0xffffffffu;

    __shared__ float red[8];
    __shared__ float s_mean, s_rs;

    float vals[7];                      // ceil(1600/256) = 7 slots
    float sum = 0.0f;
    #pragma unroll
    for (int i = 0; i < 7; i++) {
        int idx = i * 256 + t;
        float g = 0.0f;
        if (idx < BB * NDENSE) {
            int b = idx / NDENSE, d = idx % NDENSE;
            g = g_scratch[(b * CC + c) * DSTRIDE + d];
        }
        vals[i] = g;
        sum += g;
    }
    #pragma unroll
    for (int d = 16; d; d >>= 1) sum += __shfl_down_sync(full, sum, d);
    if (lane == 0) red[warp] = sum;
    __syncthreads();
    if (t == 0) {
        float tot = 0.0f;
        #pragma unroll
        for (int w = 0; w < 8; w++) tot += red[w];
        s_mean = tot * (1.0f / (BB * NBIN * NBIN));
    }
    __syncthreads();
    float mean = s_mean;

    float vs = 0.0f;
    #pragma unroll
    for (int i = 0; i < 7; i++) {
        int idx = i * 256 + t;
        if (idx < BB * NDENSE) {
            float d = vals[i] - mean;
            vs = fmaf(d, d, vs);
        }
    }
    #pragma unroll
    for (int d = 16; d; d >>= 1) vs += __shfl_down_sync(full, vs, d);
    __syncthreads();
    if (lane == 0) red[warp] = vs;
    __syncthreads();
    if (t == 0) {
        float tot = 0.0f;
        #pragma unroll
        for (int w = 0; w < 8; w++) tot += red[w];
        tot += (float)(BB * NBIN * NBIN - BB * NDENSE) * s_mean * s_mean;
        float var = tot * (1.0f / (BB * NBIN * NBIN));
        s_rs = rsqrtf(var + EPSV);
    }
    __syncthreads();
    float rs = s_rs;
    float ga = gamma[c], be = beta[c];

    for (int idx = t; idx < BB * NBIN * NBIN; idx += 256) {
        int b = idx >> 8, s = idx & 255;
        int ax = s >> 4, az = s & 15;
        float g = 0.0f;
        if (ax < 5 && az < 5)
            g = g_scratch[(b * CC + c) * DSTRIDE + ax * 5 + az];
        out[(b * CC + c) * 256 + s] = (g - mean) * rs * ga + be;
    }
}

// ---------------------------------------------------------------------------
extern "C" void kernel_launch(void* const* d_in, const int* in_sizes, int n_in,
                              void* d_out, int out_size) {
    const float* x     = (const float*)d_in[0];   // [64, 2*64^3]
    const float* gamma = (const float*)d_in[1];   // [2]
    const float* beta  = (const float*)d_in[2];   // [2]
    float* out = (float*)d_out;                   // [64,2,16,16] f32

    build_tables_kernel<<<(NVOX + 255) / 256, 256>>>();
    accumulate_kernel<<<NPAIR * SPLIT, BTHREADS>>>(x);
    gn_kernel<<<CC, 256>>>(gamma, beta, out);
}